// round 9
// baseline (speedup 1.0000x reference)
#include <cuda_runtime.h>
#include <cuda_fp16.h>
#include <cstdint>

// ---------------------------------------------------------------------------
// LocalizedFiltering via shifted-pair GEMMs on mma.sync fp16 tensor cores.
//   O1[t] = W1_0 @ x[t-1] + W1_1 @ x[t] + b1      (+ boundary fixup)
//   pre[t]= W2_0 @ O1[t-1]+ W2_1 @ O1[t]+ b2 + x[t]  (+ boundary fixup)
//   out[t]= RMSNorm(pre[t]) * gamma
// A is ONE (BM+1)-row tile; cur product reads rows shifted by +1. The 8
// sequence-start tokens are corrected exactly by tiny fixup kernels.
// BM=128 BN=128 BK=32, 8 warps 64x32, 3-stage cp.async, 2 CTAs/SM.
// Output: [lf_output total*E][lf1 B*E][lf2 B*H]
// ---------------------------------------------------------------------------

#define MAX_TOTAL 24576
#define MAX_E     2048
#define MAX_H     1024
#define MAX_B     64

#define A_TILE   8448          // 132 rows * 64B (129 used)
#define B_OFF    8448
#define B_TILE   8192          // 128 rows * 64B per variant
#define STAGE    24832         // A_TILE + 2*B_TILE
#define NSTAGE   3
#define DYN_SMEM (STAGE * NSTAGE)   // 74496 -> 2 CTAs/SM

// scratch (static __device__; no cudaMalloc allowed)
__device__ __half g_Xh [(size_t)MAX_TOTAL * MAX_E];
__device__ __half g_O1h[(size_t)MAX_TOTAL * MAX_H];
__device__ __half g_W1f[(size_t)2 * MAX_H * MAX_E]; // [var][n*E+k]
__device__ __half g_W2f[(size_t)2 * MAX_E * MAX_H]; // [var][n*H+k]
__device__ float  g_pre[(size_t)MAX_TOTAL * MAX_E];
__device__ __half g_bndXh[MAX_B * MAX_E];
__device__ __half g_bndOh[MAX_B * MAX_H];

// ---------------------------------------------------------------------------
// helpers
// ---------------------------------------------------------------------------
__device__ __forceinline__ uint32_t smem_u32(const void* p) {
    return (uint32_t)__cvta_generic_to_shared(p);
}
__device__ __forceinline__ void cp16(uint32_t dst, const void* src) {
    asm volatile("cp.async.cg.shared.global [%0], [%1], 16;" :: "r"(dst), "l"(src) : "memory");
}
__device__ __forceinline__ void cp_commit() {
    asm volatile("cp.async.commit_group;" ::: "memory");
}
__device__ __forceinline__ void cp_wait1() {
    asm volatile("cp.async.wait_group 1;" ::: "memory");
}
__device__ __forceinline__ void ldsm_x4(uint32_t* r, uint32_t a) {
    asm volatile("ldmatrix.sync.aligned.m8n8.x4.shared.b16 {%0,%1,%2,%3}, [%4];"
                 : "=r"(r[0]), "=r"(r[1]), "=r"(r[2]), "=r"(r[3]) : "r"(a));
}
__device__ __forceinline__ void mma_fp16(float* c, const uint32_t* a, const uint32_t* b) {
    asm volatile("mma.sync.aligned.m16n8k16.row.col.f32.f16.f16.f32 "
                 "{%0,%1,%2,%3}, {%4,%5,%6,%7}, {%8,%9}, {%0,%1,%2,%3};"
                 : "+f"(c[0]), "+f"(c[1]), "+f"(c[2]), "+f"(c[3])
                 : "r"(a[0]), "r"(a[1]), "r"(a[2]), "r"(a[3]), "r"(b[0]), "r"(b[1]));
}
// 64B-row tile: byte offset for (row, chunk[0..3]) conflict-free for 8-row ldsm
__device__ __forceinline__ uint32_t swz64(int row, int chunk) {
    return (uint32_t)(row * 64 + ((chunk ^ ((row >> 1) & 3)) << 4));
}

// ---------------------------------------------------------------------------
// prep kernels
// ---------------------------------------------------------------------------
__global__ void split_x_kernel(const float* __restrict__ x, size_t n)
{
    size_t i = ((size_t)blockIdx.x * blockDim.x + threadIdx.x) * 4;
    size_t stride = (size_t)gridDim.x * blockDim.x * 4;
    for (; i < n; i += stride) {
        float4 v = *(const float4*)(x + i);
        *(__half2*)(g_Xh + i)     = __floats2half2_rn(v.x, v.y);
        *(__half2*)(g_Xh + i + 2) = __floats2half2_rn(v.z, v.w);
    }
}

__global__ void pack_w_kernel(const float* __restrict__ w1,
                              const float* __restrict__ w2, int E, int H)
{
    size_t stride = (size_t)gridDim.x * blockDim.x;
    size_t i0 = (size_t)blockIdx.x * blockDim.x + threadIdx.x;
    size_t n1 = (size_t)H * E;
    for (size_t i = i0; i < n1; i += stride) {
        g_W1f[i]      = __float2half_rn(w1[i * 2]);
        g_W1f[n1 + i] = __float2half_rn(w1[i * 2 + 1]);
    }
    size_t n2 = (size_t)E * H;
    for (size_t i = i0; i < n2; i += stride) {
        g_W2f[i]      = __float2half_rn(w2[i * 2]);
        g_W2f[n2 + i] = __float2half_rn(w2[i * 2 + 1]);
    }
}

__global__ void prep_bnd_kernel(const float* __restrict__ lf1,
                                const float* __restrict__ lf2,
                                const float* __restrict__ w1,
                                const float* __restrict__ b1,
                                const int*   __restrict__ lens,
                                const int*   __restrict__ maxlen_ptr,
                                int E, int H)
{
    int b = blockIdx.x;
    int L = lens[b];
    int ml = maxlen_ptr ? maxlen_ptr[0] : 4096;
    bool full = (L == ml);
    for (int i = threadIdx.x; i < E; i += blockDim.x) {
        float v = full ? lf1[(size_t)b * E + i] : 0.f;
        g_bndXh[(size_t)b * E + i] = __float2half_rn(v);
    }
    int s0 = ml - L;
    for (int n = threadIdx.x; n < H; n += blockDim.x) {
        float v;
        if (full) {
            v = lf2[(size_t)b * H + n];
        } else {
            v = b1[n];
            if (s0 == 1) {
                const float* wr = w1 + (size_t)n * E * 2;
                float acc = 0.f;
                for (int k = 0; k < E; k++) acc += wr[(size_t)k * 2] * lf1[(size_t)b * E + k];
                v += acc;
            }
        }
        g_bndOh[(size_t)b * H + n] = __float2half_rn(v);
    }
}

// ---------------------------------------------------------------------------
// GEMM: C[t,n] = W0 @ A[t-1] + W1 @ A[t]  (+bias, +resid). A tile has BM+1
// rows (row j = token m0-1+j, clamped to [0, M-1]); prev reads j, cur j+1.
// ---------------------------------------------------------------------------
template<bool STAGE2>
__global__ __launch_bounds__(256, 2)
void conv_tc(const __half* __restrict__ srcH,
             const __half* __restrict__ Wf, size_t wvar,
             const float* __restrict__ bias,
             const float* __restrict__ resid,
             int M, int Nfull, int K,
             float* __restrict__ outF,
             __half* __restrict__ outH)
{
    extern __shared__ char sm[];
    const uint32_t sbase = smem_u32(sm);
    const int tid = threadIdx.x;
    const int lane = tid & 31;
    const int wid = tid >> 5;
    const int m0 = blockIdx.y * 128;
    const int n0 = blockIdx.x * 128;

    // ---- A loader: 129 rows x 4 chunks = 516 cp16 over 256 threads (<=3 ea)
    const __half* aptr[3]; uint32_t adst[3]; bool aval[3];
    #pragma unroll
    for (int i = 0; i < 3; i++) {
        int s = tid + i * 256;
        aval[i] = (s < 516);
        int row = aval[i] ? (s >> 2) : 0;
        int c   = s & 3;
        int tok = m0 - 1 + row;
        if (tok < 0) tok = 0;
        if (tok >= M) tok = M - 1;
        aptr[i] = srcH + (size_t)tok * K + c * 8;
        adst[i] = swz64(row, c);
    }
    // ---- B loader: 2 variants x 128 rows x 4 chunks = 1024 cp16 (4 each)
    const __half* bptr[4]; uint32_t bdst[4];
    #pragma unroll
    for (int i = 0; i < 4; i++) {
        int s = tid + i * 256;
        int var = s >> 9;
        int row = (s >> 2) & 127;
        int c   = s & 3;
        bptr[i] = Wf + (size_t)var * wvar + (size_t)(n0 + row) * K + c * 8;
        bdst[i] = (uint32_t)(B_OFF + var * B_TILE) + swz64(row, c);
    }

    // ---- mma lane constants: 8 warps, 2 m-bands x 4 n-bands of 64x32 -------
    const int wm = wid & 1;
    const int wn = wid >> 1;
    const int mbase = wm * 64;
    const int nbase = wn * 32;
    const int a_row_off = ((lane >> 3) & 1) * 8 + (lane & 7);
    const int a_kh = lane >> 4;
    const int b_row_off = ((lane >> 4) & 1) * 8 + (lane & 7);
    const int b_h = (lane >> 3) & 1;

    float acc[4][4][4];
    #pragma unroll
    for (int mi = 0; mi < 4; mi++)
        #pragma unroll
        for (int ni = 0; ni < 4; ni++)
            #pragma unroll
            for (int e = 0; e < 4; e++) acc[mi][ni][e] = 0.f;

    auto issue = [&](int it) {
        uint32_t sb = sbase + (it % NSTAGE) * STAGE;
        int koff = it * 32;
        #pragma unroll
        for (int i = 0; i < 3; i++)
            if (aval[i]) cp16(sb + adst[i], aptr[i] + koff);
        #pragma unroll
        for (int i = 0; i < 4; i++)
            cp16(sb + bdst[i], bptr[i] + koff);
        cp_commit();
    };

    const int niter = K >> 5;
    issue(0); issue(1);

    for (int it = 0; it < niter; ++it) {
        cp_wait1();               // group it complete
        __syncthreads();          // slot (it+2)%3 free (computed at it-1)
        if (it + 2 < niter) issue(it + 2);
        else cp_commit();         // empty group keeps count uniform

        const uint32_t base = sbase + (it % NSTAGE) * STAGE;
        #pragma unroll
        for (int ks = 0; ks < 2; ks++) {
            // B fragments: 2 variants x 2 ldsm_x4 covering 32 n
            uint32_t bb[2][8];
            #pragma unroll
            for (int v = 0; v < 2; v++)
                #pragma unroll
                for (int g = 0; g < 2; g++) {
                    int row = nbase + g * 16 + b_row_off;
                    ldsm_x4(&bb[v][g * 4],
                            base + B_OFF + v * B_TILE + swz64(row, ks * 2 + b_h));
                }
            // products: prev (A rows j) -> W0, cur (A rows j+1) -> W1
            #pragma unroll
            for (int av = 0; av < 2; av++) {
                uint32_t a[4][4];
                #pragma unroll
                for (int mi = 0; mi < 4; mi++) {
                    int j = mbase + mi * 16 + a_row_off + av;
                    ldsm_x4(a[mi], base + swz64(j, ks * 2 + a_kh));
                }
                #pragma unroll
                for (int ni = 0; ni < 4; ni++)
                    #pragma unroll
                    for (int mi = 0; mi < 4; mi++)
                        mma_fp16(acc[mi][ni], a[mi], &bb[av][ni * 2]);
            }
        }
    }

    // ---- epilogue ----------------------------------------------------------
    const int erow = lane >> 2;
    const int ecol = (lane & 3) * 2;
    #pragma unroll
    for (int mi = 0; mi < 4; mi++) {
        int r0 = m0 + mbase + mi * 16 + erow;
        int r1 = r0 + 8;
        #pragma unroll
        for (int ni = 0; ni < 4; ni++) {
            int c = n0 + nbase + ni * 8 + ecol;
            float bx = bias[c], by = bias[c + 1];
            float v00 = acc[mi][ni][0] + bx, v01 = acc[mi][ni][1] + by;
            float v10 = acc[mi][ni][2] + bx, v11 = acc[mi][ni][3] + by;
            if (STAGE2) {
                if (r0 < M) {
                    float2 rr = *(const float2*)(resid + (size_t)r0 * Nfull + c);
                    *(float2*)(outF + (size_t)r0 * Nfull + c) =
                        make_float2(v00 + rr.x, v01 + rr.y);
                }
                if (r1 < M) {
                    float2 rr = *(const float2*)(resid + (size_t)r1 * Nfull + c);
                    *(float2*)(outF + (size_t)r1 * Nfull + c) =
                        make_float2(v10 + rr.x, v11 + rr.y);
                }
            } else {
                if (r0 < M)
                    *(__half2*)(outH + (size_t)r0 * Nfull + c) = __floats2half2_rn(v00, v01);
                if (r1 < M)
                    *(__half2*)(outH + (size_t)r1 * Nfull + c) = __floats2half2_rn(v10, v11);
            }
        }
    }
}

// ---------------------------------------------------------------------------
// fixups: correct prev-product at the B sequence-start tokens (exact).
// ---------------------------------------------------------------------------
__global__ void fixup1_kernel(const int* __restrict__ start, int E, int H)
{
    int b = blockIdx.x;
    int t = start[b];
    int tp = (t > 0) ? (t - 1) : 0;
    const __half* xu = g_Xh + (size_t)tp * E;
    const __half* xb = g_bndXh + (size_t)b * E;
    for (int n = threadIdx.x; n < H; n += blockDim.x) {
        const __half* w = g_W1f + (size_t)n * E;   // variant 0 (W1_0)
        float acc = 0.f;
        for (int k = 0; k < E; k += 2) {
            float2 d  = __half22float2(__hsub2(*(const __half2*)(xb + k),
                                               *(const __half2*)(xu + k)));
            float2 wf = __half22float2(*(const __half2*)(w + k));
            acc += d.x * wf.x + d.y * wf.y;
        }
        size_t o = (size_t)t * H + n;
        g_O1h[o] = __float2half_rn(__half2float(g_O1h[o]) + acc);
    }
}

__global__ void fixup2_kernel(const int* __restrict__ start, int E, int H)
{
    int b = blockIdx.x;
    int t = start[b];
    int tp = (t > 0) ? (t - 1) : 0;
    const __half* ou = g_O1h + (size_t)tp * H;     // post-fixup1 values
    const __half* ob = g_bndOh + (size_t)b * H;
    for (int n = threadIdx.x; n < E; n += blockDim.x) {
        const __half* w = g_W2f + (size_t)n * H;   // variant 0 (W2_0)
        float acc = 0.f;
        for (int k = 0; k < H; k += 2) {
            float2 d  = __half22float2(__hsub2(*(const __half2*)(ob + k),
                                               *(const __half2*)(ou + k)));
            float2 wf = __half22float2(*(const __half2*)(w + k));
            acc += d.x * wf.x + d.y * wf.y;
        }
        g_pre[(size_t)t * E + n] += acc;
    }
}

// ---------------------------------------------------------------------------
__global__ __launch_bounds__(256)
void rmsnorm_kernel(const float* __restrict__ pre,
                    const float* __restrict__ gamma,
                    float* __restrict__ out, int E, float invE)
{
    int t = blockIdx.x;
    const float* row = pre + (size_t)t * E;
    float ss = 0.f;
    for (int i = threadIdx.x * 4; i < E; i += blockDim.x * 4) {
        float4 v = *(const float4*)(row + i);
        ss += v.x * v.x + v.y * v.y + v.z * v.z + v.w * v.w;
    }
    __shared__ float red[32];
    #pragma unroll
    for (int o = 16; o; o >>= 1) ss += __shfl_xor_sync(~0u, ss, o);
    if ((threadIdx.x & 31) == 0) red[threadIdx.x >> 5] = ss;
    __syncthreads();
    if (threadIdx.x < 32) {
        float v = (threadIdx.x < (blockDim.x >> 5)) ? red[threadIdx.x] : 0.f;
        #pragma unroll
        for (int o = 16; o; o >>= 1) v += __shfl_xor_sync(~0u, v, o);
        if (threadIdx.x == 0) red[0] = v;
    }
    __syncthreads();
    float scale = rsqrtf(red[0] * invE + 1e-6f);
    for (int i = threadIdx.x * 4; i < E; i += blockDim.x * 4) {
        float4 v = *(const float4*)(row + i);
        float4 g = *(const float4*)(gamma + i);
        v.x *= scale * g.x; v.y *= scale * g.y;
        v.z *= scale * g.z; v.w *= scale * g.w;
        *(float4*)(out + (size_t)t * E + i) = v;
    }
}

__global__ void lf_kernel(const float* __restrict__ inputs,
                          const int* __restrict__ start,
                          const int* __restrict__ lens,
                          int B, int E, int H, int total,
                          float* __restrict__ out, long long out_size)
{
    int b = blockIdx.x;
    int last = start[b] + lens[b] - 1;
    long long base1 = (long long)total * E;
    long long base2 = base1 + (long long)B * E;
    for (int i = threadIdx.x; i < E; i += blockDim.x) {
        long long o = base1 + (long long)b * E + i;
        if (o < out_size) out[o] = inputs[(size_t)last * E + i];
    }
    for (int n = threadIdx.x; n < H; n += blockDim.x) {
        long long o = base2 + (long long)b * H + n;
        if (o < out_size) out[o] = __half2float(g_O1h[(size_t)last * H + n]);
    }
}

__global__ void fallback_kernel(float* out, int n) {
    int i = blockIdx.x * blockDim.x + threadIdx.x;
    if (i < n) out[i] = 0.f;
}

// ---------------------------------------------------------------------------
extern "C" void kernel_launch(void* const* d_in, const int* in_sizes, int n_in,
                              void* d_out, int out_size)
{
    const float* inputs = (const float*)d_in[0];
    const float* lf1    = (const float*)d_in[1];
    const float* lf2    = (const float*)d_in[2];
    const float* w1     = (const float*)d_in[3];
    const float* b1     = (const float*)d_in[4];
    const float* w2     = (const float*)d_in[5];
    const float* b2     = (const float*)d_in[6];
    const float* gamma  = (const float*)d_in[7];
    const int*   start  = (const int*)d_in[8];
    const int*   lens   = (const int*)d_in[9];
    const int*   maxlen = (n_in > 10) ? (const int*)d_in[10] : nullptr;

    const int E = in_sizes[7];
    const int H = in_sizes[4];
    const int total = in_sizes[0] / E;
    const int B = in_sizes[9];
    float* out = (float*)d_out;

    if (E > MAX_E || H > MAX_H || total > MAX_TOTAL || B > MAX_B ||
        (E & 127) || (H & 127) || (E & 31) || (H & 31)) {
        fallback_kernel<<<(out_size + 255) / 256, 256>>>(out, out_size);
        return;
    }

    __half *pXh, *pO1h, *pW1f, *pW2f;
    float *pPre;
    cudaGetSymbolAddress((void**)&pXh,  g_Xh);
    cudaGetSymbolAddress((void**)&pO1h, g_O1h);
    cudaGetSymbolAddress((void**)&pW1f, g_W1f);
    cudaGetSymbolAddress((void**)&pW2f, g_W2f);
    cudaGetSymbolAddress((void**)&pPre, g_pre);

    cudaFuncSetAttribute(conv_tc<false>, cudaFuncAttributeMaxDynamicSharedMemorySize, DYN_SMEM);
    cudaFuncSetAttribute(conv_tc<true>,  cudaFuncAttributeMaxDynamicSharedMemorySize, DYN_SMEM);

    split_x_kernel<<<512, 256>>>(inputs, (size_t)total * E);
    pack_w_kernel<<<512, 256>>>(w1, w2, E, H);
    prep_bnd_kernel<<<B, 256>>>(lf1, lf2, w1, b1, lens, maxlen, E, H);

    // Stage 1: O1 = X[t-1]@W1_0 + X[t]@W1_1 + b1   (M=total, N=H, K=E)
    {
        dim3 grid(H / 128, (total + 127) / 128);
        conv_tc<false><<<grid, 256, DYN_SMEM>>>(pXh, pW1f, (size_t)H * E,
                                                b1, nullptr,
                                                total, H, E,
                                                nullptr, pO1h);
    }
    fixup1_kernel<<<B, 256>>>(start, E, H);
    // Stage 2: pre = O1[t-1]@W2_0 + O1[t]@W2_1 + b2 + x  (M=total, N=E, K=H)
    {
        dim3 grid(E / 128, (total + 127) / 128);
        conv_tc<true><<<grid, 256, DYN_SMEM>>>(pO1h, pW2f, (size_t)E * H,
                                               b2, inputs,
                                               total, E, H,
                                               pPre, nullptr);
    }
    fixup2_kernel<<<B, 256>>>(start, E, H);
    rmsnorm_kernel<<<total, 256>>>(pPre, gamma, out, E, 1.f / (float)E);
    lf_kernel<<<B, 256>>>(inputs, start, lens, B, E, H, total,
                          out, (long long)out_size);
}

// round 10
// speedup vs baseline: 1.0004x; 1.0004x over previous
#include <cuda_runtime.h>
#include <cuda_fp16.h>
#include <cstdint>

// ---------------------------------------------------------------------------
// LocalizedFiltering via shifted-pair GEMMs on mma.sync fp16 tensor cores.
//   O1[t] = W1_0 @ x[t-1] + W1_1 @ x[t] + b1      (+ boundary fixup)
//   pre[t]= W2_0 @ O1[t-1]+ W2_1 @ O1[t]+ b2         (+ boundary fixup)
//   out[t]= RMSNorm(pre[t] + x[t]) * gamma           (resid fused here)
// A is ONE (BM+1)-row tile; cur product reads rows shifted by +1. The 8
// sequence-start tokens are corrected exactly by tiny fixup kernels.
// BM=128 BN=128 BK=32, 8 warps 64x32, 3-stage cp.async, 2 CTAs/SM.
// Loader state kept as 32-bit offsets to stay under the 128-reg cap.
// Output: [lf_output total*E][lf1 B*E][lf2 B*H]
// ---------------------------------------------------------------------------

#define MAX_TOTAL 24576
#define MAX_E     2048
#define MAX_H     1024
#define MAX_B     64

#define A_TILE   8448          // 132 rows * 64B (129 used)
#define B_OFF    8448
#define B_TILE   8192          // 128 rows * 64B per variant
#define STAGE    24832         // A_TILE + 2*B_TILE
#define NSTAGE   3
#define DYN_SMEM (STAGE * NSTAGE)   // 74496 -> 2 CTAs/SM

// scratch (static __device__; no cudaMalloc allowed)
__device__ __half g_Xh [(size_t)MAX_TOTAL * MAX_E];
__device__ __half g_O1h[(size_t)MAX_TOTAL * MAX_H];
__device__ __half g_W1f[(size_t)2 * MAX_H * MAX_E]; // [var][n*E+k]
__device__ __half g_W2f[(size_t)2 * MAX_E * MAX_H]; // [var][n*H+k]
__device__ float  g_pre[(size_t)MAX_TOTAL * MAX_E];
__device__ __half g_bndXh[MAX_B * MAX_E];
__device__ __half g_bndOh[MAX_B * MAX_H];

// ---------------------------------------------------------------------------
// helpers
// ---------------------------------------------------------------------------
__device__ __forceinline__ uint32_t smem_u32(const void* p) {
    return (uint32_t)__cvta_generic_to_shared(p);
}
__device__ __forceinline__ void cp16(uint32_t dst, const void* src) {
    asm volatile("cp.async.cg.shared.global [%0], [%1], 16;" :: "r"(dst), "l"(src) : "memory");
}
__device__ __forceinline__ void cp_commit() {
    asm volatile("cp.async.commit_group;" ::: "memory");
}
__device__ __forceinline__ void cp_wait1() {
    asm volatile("cp.async.wait_group 1;" ::: "memory");
}
__device__ __forceinline__ void ldsm_x4(uint32_t* r, uint32_t a) {
    asm volatile("ldmatrix.sync.aligned.m8n8.x4.shared.b16 {%0,%1,%2,%3}, [%4];"
                 : "=r"(r[0]), "=r"(r[1]), "=r"(r[2]), "=r"(r[3]) : "r"(a));
}
__device__ __forceinline__ void mma_fp16(float* c, const uint32_t* a, const uint32_t* b) {
    asm volatile("mma.sync.aligned.m16n8k16.row.col.f32.f16.f16.f32 "
                 "{%0,%1,%2,%3}, {%4,%5,%6,%7}, {%8,%9}, {%0,%1,%2,%3};"
                 : "+f"(c[0]), "+f"(c[1]), "+f"(c[2]), "+f"(c[3])
                 : "r"(a[0]), "r"(a[1]), "r"(a[2]), "r"(a[3]), "r"(b[0]), "r"(b[1]));
}
// 64B-row tile: byte offset for (row, chunk[0..3]) conflict-free for 8-row ldsm
__device__ __forceinline__ uint32_t swz64(int row, int chunk) {
    return (uint32_t)(row * 64 + ((chunk ^ ((row >> 1) & 3)) << 4));
}

// ---------------------------------------------------------------------------
// prep kernels
// ---------------------------------------------------------------------------
__global__ void split_x_kernel(const float* __restrict__ x, size_t n)
{
    size_t i = ((size_t)blockIdx.x * blockDim.x + threadIdx.x) * 4;
    size_t stride = (size_t)gridDim.x * blockDim.x * 4;
    for (; i < n; i += stride) {
        float4 v = *(const float4*)(x + i);
        *(__half2*)(g_Xh + i)     = __floats2half2_rn(v.x, v.y);
        *(__half2*)(g_Xh + i + 2) = __floats2half2_rn(v.z, v.w);
    }
}

__global__ void pack_w_kernel(const float* __restrict__ w1,
                              const float* __restrict__ w2, int E, int H)
{
    size_t stride = (size_t)gridDim.x * blockDim.x;
    size_t i0 = (size_t)blockIdx.x * blockDim.x + threadIdx.x;
    size_t n1 = (size_t)H * E;
    for (size_t i = i0; i < n1; i += stride) {
        g_W1f[i]      = __float2half_rn(w1[i * 2]);
        g_W1f[n1 + i] = __float2half_rn(w1[i * 2 + 1]);
    }
    size_t n2 = (size_t)E * H;
    for (size_t i = i0; i < n2; i += stride) {
        g_W2f[i]      = __float2half_rn(w2[i * 2]);
        g_W2f[n2 + i] = __float2half_rn(w2[i * 2 + 1]);
    }
}

__global__ void prep_bnd_kernel(const float* __restrict__ lf1,
                                const float* __restrict__ lf2,
                                const float* __restrict__ w1,
                                const float* __restrict__ b1,
                                const int*   __restrict__ lens,
                                const int*   __restrict__ maxlen_ptr,
                                int E, int H)
{
    int b = blockIdx.x;
    int L = lens[b];
    int ml = maxlen_ptr ? maxlen_ptr[0] : 4096;
    bool full = (L == ml);
    for (int i = threadIdx.x; i < E; i += blockDim.x) {
        float v = full ? lf1[(size_t)b * E + i] : 0.f;
        g_bndXh[(size_t)b * E + i] = __float2half_rn(v);
    }
    int s0 = ml - L;
    for (int n = threadIdx.x; n < H; n += blockDim.x) {
        float v;
        if (full) {
            v = lf2[(size_t)b * H + n];
        } else {
            v = b1[n];
            if (s0 == 1) {
                const float* wr = w1 + (size_t)n * E * 2;
                float acc = 0.f;
                for (int k = 0; k < E; k++) acc += wr[(size_t)k * 2] * lf1[(size_t)b * E + k];
                v += acc;
            }
        }
        g_bndOh[(size_t)b * H + n] = __float2half_rn(v);
    }
}

// ---------------------------------------------------------------------------
// GEMM: C[t,n] = W0 @ A[t-1] + W1 @ A[t]  (+bias). A tile has BM+1 rows
// (row j = token m0-1+j, clamped to [0, M-1]); prev reads j, cur j+1.
// ---------------------------------------------------------------------------
template<bool STAGE2>
__global__ __launch_bounds__(256, 2)
void conv_tc(const __half* __restrict__ srcH,
             const __half* __restrict__ Wf,
             const float* __restrict__ bias,
             int M, int Nfull, int K, uint32_t wvar,
             float* __restrict__ outF,
             __half* __restrict__ outH)
{
    extern __shared__ char sm[];
    const uint32_t sbase = smem_u32(sm);
    const int tid = threadIdx.x;
    const int lane = tid & 31;
    const int wid = tid >> 5;
    const int m0 = blockIdx.y * 128;
    const int n0 = blockIdx.x * 128;

    // ---- A loader: 129 rows x 4 chunks = 516 cp16 over 256 threads (<=3 ea)
    uint32_t aoff[3]; uint32_t adst[3]; bool aval[3];
    #pragma unroll
    for (int i = 0; i < 3; i++) {
        int s = tid + i * 256;
        aval[i] = (s < 516);
        int row = aval[i] ? (s >> 2) : 0;
        int c   = s & 3;
        int tok = m0 - 1 + row;
        if (tok < 0) tok = 0;
        if (tok >= M) tok = M - 1;
        aoff[i] = (uint32_t)tok * (uint32_t)K + (uint32_t)(c * 8);
        adst[i] = swz64(row, c);
    }
    // ---- B loader: 2 variants x 128 rows x 4 chunks = 1024 cp16 (4 each)
    uint32_t boff[4]; uint32_t bdst[4];
    #pragma unroll
    for (int i = 0; i < 4; i++) {
        int s = tid + i * 256;
        int var = s >> 9;
        int row = (s >> 2) & 127;
        int c   = s & 3;
        boff[i] = (uint32_t)var * wvar + (uint32_t)(n0 + row) * (uint32_t)K
                + (uint32_t)(c * 8);
        bdst[i] = (uint32_t)(B_OFF + var * B_TILE) + swz64(row, c);
    }

    // ---- mma lane constants: 8 warps, 2 m-bands x 4 n-bands of 64x32 -------
    const int wm = wid & 1;
    const int wn = wid >> 1;
    const int mbase = wm * 64;
    const int nbase = wn * 32;
    const int a_row_off = ((lane >> 3) & 1) * 8 + (lane & 7);
    const int a_kh = lane >> 4;
    const int b_row_off = ((lane >> 4) & 1) * 8 + (lane & 7);
    const int b_h = (lane >> 3) & 1;

    float acc[4][4][4];
    #pragma unroll
    for (int mi = 0; mi < 4; mi++)
        #pragma unroll
        for (int ni = 0; ni < 4; ni++)
            #pragma unroll
            for (int e = 0; e < 4; e++) acc[mi][ni][e] = 0.f;

    auto issue = [&](int it) {
        uint32_t sb = sbase + (it % NSTAGE) * STAGE;
        uint32_t koff = (uint32_t)it * 32u;
        #pragma unroll
        for (int i = 0; i < 3; i++)
            if (aval[i]) cp16(sb + adst[i], srcH + aoff[i] + koff);
        #pragma unroll
        for (int i = 0; i < 4; i++)
            cp16(sb + bdst[i], Wf + boff[i] + koff);
        cp_commit();
    };

    const int niter = K >> 5;
    issue(0); issue(1);

    for (int it = 0; it < niter; ++it) {
        cp_wait1();               // group it complete
        __syncthreads();          // slot (it+2)%3 free (computed at it-1)
        if (it + 2 < niter) issue(it + 2);
        else cp_commit();         // empty group keeps count uniform

        const uint32_t base = sbase + (it % NSTAGE) * STAGE;
        #pragma unroll
        for (int ks = 0; ks < 2; ks++) {
            // B fragments: 2 variants x 2 ldsm_x4 covering 32 n
            uint32_t bb[2][8];
            #pragma unroll
            for (int v = 0; v < 2; v++)
                #pragma unroll
                for (int g = 0; g < 2; g++) {
                    int row = nbase + g * 16 + b_row_off;
                    ldsm_x4(&bb[v][g * 4],
                            base + B_OFF + v * B_TILE + swz64(row, ks * 2 + b_h));
                }
            // products: prev (A rows j) -> W0, cur (A rows j+1) -> W1
            #pragma unroll
            for (int av = 0; av < 2; av++) {
                uint32_t a[4][4];
                #pragma unroll
                for (int mi = 0; mi < 4; mi++) {
                    int j = mbase + mi * 16 + a_row_off + av;
                    ldsm_x4(a[mi], base + swz64(j, ks * 2 + a_kh));
                }
                #pragma unroll
                for (int ni = 0; ni < 4; ni++)
                    #pragma unroll
                    for (int mi = 0; mi < 4; mi++)
                        mma_fp16(acc[mi][ni], a[mi], &bb[av][ni * 2]);
            }
        }
    }

    // ---- epilogue (no resid: both stages identical footprint) --------------
    const int erow = lane >> 2;
    const int ecol = (lane & 3) * 2;
    #pragma unroll
    for (int mi = 0; mi < 4; mi++) {
        int r0 = m0 + mbase + mi * 16 + erow;
        int r1 = r0 + 8;
        #pragma unroll
        for (int ni = 0; ni < 4; ni++) {
            int c = n0 + nbase + ni * 8 + ecol;
            float bx = bias[c], by = bias[c + 1];
            float v00 = acc[mi][ni][0] + bx, v01 = acc[mi][ni][1] + by;
            float v10 = acc[mi][ni][2] + bx, v11 = acc[mi][ni][3] + by;
            if (STAGE2) {
                if (r0 < M)
                    *(float2*)(outF + (size_t)r0 * Nfull + c) = make_float2(v00, v01);
                if (r1 < M)
                    *(float2*)(outF + (size_t)r1 * Nfull + c) = make_float2(v10, v11);
            } else {
                if (r0 < M)
                    *(__half2*)(outH + (size_t)r0 * Nfull + c) = __floats2half2_rn(v00, v01);
                if (r1 < M)
                    *(__half2*)(outH + (size_t)r1 * Nfull + c) = __floats2half2_rn(v10, v11);
            }
        }
    }
}

// ---------------------------------------------------------------------------
// fixups: correct prev-product at the B sequence-start tokens (exact).
// ---------------------------------------------------------------------------
__global__ void fixup1_kernel(const int* __restrict__ start, int E, int H)
{
    int b = blockIdx.x;
    int t = start[b];
    int tp = (t > 0) ? (t - 1) : 0;
    const __half* xu = g_Xh + (size_t)tp * E;
    const __half* xb = g_bndXh + (size_t)b * E;
    for (int n = threadIdx.x; n < H; n += blockDim.x) {
        const __half* w = g_W1f + (size_t)n * E;   // variant 0 (W1_0)
        float acc = 0.f;
        for (int k = 0; k < E; k += 2) {
            float2 d  = __half22float2(__hsub2(*(const __half2*)(xb + k),
                                               *(const __half2*)(xu + k)));
            float2 wf = __half22float2(*(const __half2*)(w + k));
            acc += d.x * wf.x + d.y * wf.y;
        }
        size_t o = (size_t)t * H + n;
        g_O1h[o] = __float2half_rn(__half2float(g_O1h[o]) + acc);
    }
}

__global__ void fixup2_kernel(const int* __restrict__ start, int E, int H)
{
    int b = blockIdx.x;
    int t = start[b];
    int tp = (t > 0) ? (t - 1) : 0;
    const __half* ou = g_O1h + (size_t)tp * H;     // post-fixup1 values
    const __half* ob = g_bndOh + (size_t)b * H;
    for (int n = threadIdx.x; n < E; n += blockDim.x) {
        const __half* w = g_W2f + (size_t)n * H;   // variant 0 (W2_0)
        float acc = 0.f;
        for (int k = 0; k < H; k += 2) {
            float2 d  = __half22float2(__hsub2(*(const __half2*)(ob + k),
                                               *(const __half2*)(ou + k)));
            float2 wf = __half22float2(*(const __half2*)(w + k));
            acc += d.x * wf.x + d.y * wf.y;
        }
        g_pre[(size_t)t * E + n] += acc;
    }
}

// ---------------------------------------------------------------------------
// rmsnorm with fused residual: out = gamma * (pre + x) * rsqrt(mean((pre+x)^2))
// ---------------------------------------------------------------------------
__global__ __launch_bounds__(256)
void rmsnorm_kernel(const float* __restrict__ pre,
                    const float* __restrict__ x,
                    const float* __restrict__ gamma,
                    float* __restrict__ out, int E, float invE)
{
    __shared__ float srow[MAX_E];
    __shared__ float red[32];
    int t = blockIdx.x;
    const float* prow = pre + (size_t)t * E;
    const float* xrow = x + (size_t)t * E;
    float ss = 0.f;
    for (int i = threadIdx.x * 4; i < E; i += blockDim.x * 4) {
        float4 p = *(const float4*)(prow + i);
        float4 r = *(const float4*)(xrow + i);
        p.x += r.x; p.y += r.y; p.z += r.z; p.w += r.w;
        *(float4*)(srow + i) = p;
        ss += p.x * p.x + p.y * p.y + p.z * p.z + p.w * p.w;
    }
    #pragma unroll
    for (int o = 16; o; o >>= 1) ss += __shfl_xor_sync(~0u, ss, o);
    if ((threadIdx.x & 31) == 0) red[threadIdx.x >> 5] = ss;
    __syncthreads();
    if (threadIdx.x < 32) {
        float v = (threadIdx.x < (blockDim.x >> 5)) ? red[threadIdx.x] : 0.f;
        #pragma unroll
        for (int o = 16; o; o >>= 1) v += __shfl_xor_sync(~0u, v, o);
        if (threadIdx.x == 0) red[0] = v;
    }
    __syncthreads();
    float scale = rsqrtf(red[0] * invE + 1e-6f);
    for (int i = threadIdx.x * 4; i < E; i += blockDim.x * 4) {
        float4 p = *(const float4*)(srow + i);
        float4 g = *(const float4*)(gamma + i);
        p.x *= scale * g.x; p.y *= scale * g.y;
        p.z *= scale * g.z; p.w *= scale * g.w;
        *(float4*)(out + (size_t)t * E + i) = p;
    }
}

__global__ void lf_kernel(const float* __restrict__ inputs,
                          const int* __restrict__ start,
                          const int* __restrict__ lens,
                          int B, int E, int H, int total,
                          float* __restrict__ out, long long out_size)
{
    int b = blockIdx.x;
    int last = start[b] + lens[b] - 1;
    long long base1 = (long long)total * E;
    long long base2 = base1 + (long long)B * E;
    for (int i = threadIdx.x; i < E; i += blockDim.x) {
        long long o = base1 + (long long)b * E + i;
        if (o < out_size) out[o] = inputs[(size_t)last * E + i];
    }
    for (int n = threadIdx.x; n < H; n += blockDim.x) {
        long long o = base2 + (long long)b * H + n;
        if (o < out_size) out[o] = __half2float(g_O1h[(size_t)last * H + n]);
    }
}

__global__ void fallback_kernel(float* out, int n) {
    int i = blockIdx.x * blockDim.x + threadIdx.x;
    if (i < n) out[i] = 0.f;
}

// ---------------------------------------------------------------------------
extern "C" void kernel_launch(void* const* d_in, const int* in_sizes, int n_in,
                              void* d_out, int out_size)
{
    const float* inputs = (const float*)d_in[0];
    const float* lf1    = (const float*)d_in[1];
    const float* lf2    = (const float*)d_in[2];
    const float* w1     = (const float*)d_in[3];
    const float* b1     = (const float*)d_in[4];
    const float* w2     = (const float*)d_in[5];
    const float* b2     = (const float*)d_in[6];
    const float* gamma  = (const float*)d_in[7];
    const int*   start  = (const int*)d_in[8];
    const int*   lens   = (const int*)d_in[9];
    const int*   maxlen = (n_in > 10) ? (const int*)d_in[10] : nullptr;

    const int E = in_sizes[7];
    const int H = in_sizes[4];
    const int total = in_sizes[0] / E;
    const int B = in_sizes[9];
    float* out = (float*)d_out;

    if (E > MAX_E || H > MAX_H || total > MAX_TOTAL || B > MAX_B ||
        (E & 127) || (H & 127) || (E & 31) || (H & 31)) {
        fallback_kernel<<<(out_size + 255) / 256, 256>>>(out, out_size);
        return;
    }

    __half *pXh, *pO1h, *pW1f, *pW2f;
    float *pPre;
    cudaGetSymbolAddress((void**)&pXh,  g_Xh);
    cudaGetSymbolAddress((void**)&pO1h, g_O1h);
    cudaGetSymbolAddress((void**)&pW1f, g_W1f);
    cudaGetSymbolAddress((void**)&pW2f, g_W2f);
    cudaGetSymbolAddress((void**)&pPre, g_pre);

    cudaFuncSetAttribute(conv_tc<false>, cudaFuncAttributeMaxDynamicSharedMemorySize, DYN_SMEM);
    cudaFuncSetAttribute(conv_tc<true>,  cudaFuncAttributeMaxDynamicSharedMemorySize, DYN_SMEM);

    split_x_kernel<<<512, 256>>>(inputs, (size_t)total * E);
    pack_w_kernel<<<512, 256>>>(w1, w2, E, H);
    prep_bnd_kernel<<<B, 256>>>(lf1, lf2, w1, b1, lens, maxlen, E, H);

    // Stage 1: O1 = X[t-1]@W1_0 + X[t]@W1_1 + b1   (M=total, N=H, K=E)
    {
        dim3 grid(H / 128, (total + 127) / 128);
        conv_tc<false><<<grid, 256, DYN_SMEM>>>(pXh, pW1f, b1,
                                                total, H, E, (uint32_t)(H * E),
                                                nullptr, pO1h);
    }
    fixup1_kernel<<<B, 256>>>(start, E, H);
    // Stage 2: pre = O1[t-1]@W2_0 + O1[t]@W2_1 + b2  (M=total, N=E, K=H)
    {
        dim3 grid(E / 128, (total + 127) / 128);
        conv_tc<true><<<grid, 256, DYN_SMEM>>>(pO1h, pW2f, b2,
                                               total, E, H, (uint32_t)(E * H),
                                               pPre, nullptr);
    }
    fixup2_kernel<<<B, 256>>>(start, E, H);
    rmsnorm_kernel<<<total, 256>>>(pPre, inputs, gamma, out, E, 1.f / (float)E);
    lf_kernel<<<B, 256>>>(inputs, start, lens, B, E, H, total,
                          out, (long long)out_size);
}

// round 11
// speedup vs baseline: 1.8718x; 1.8711x over previous
#include <cuda_runtime.h>
#include <cuda_fp16.h>
#include <cstdint>

// ---------------------------------------------------------------------------
// LocalizedFiltering via shifted-pair GEMMs on mma.sync fp16 tensor cores.
//   O1[t] = W1_0 @ x[t-1] + W1_1 @ x[t] + b1      (+ boundary fixup)
//   pre[t]= W2_0 @ O1[t-1]+ W2_1 @ O1[t]+ b2         (+ boundary fixup)
//   out[t]= RMSNorm(pre[t] + x[t]) * gamma           (resid fused here)
// A is ONE (BM+1)-row tile; cur product reads rows shifted by +1. The 8
// sequence-start tokens are corrected exactly by warp-per-output fixup
// kernels (coalesced weight reads, full-chip grids).
// BM=128 BN=128 BK=32, 8 warps 64x32, 3-stage cp.async, 2 CTAs/SM.
// Output: [lf_output total*E][lf1 B*E][lf2 B*H]
// ---------------------------------------------------------------------------

#define MAX_TOTAL 24576
#define MAX_E     2048
#define MAX_H     1024
#define MAX_B     64

#define A_TILE   8448          // 132 rows * 64B (129 used)
#define B_OFF    8448
#define B_TILE   8192          // 128 rows * 64B per variant
#define STAGE    24832         // A_TILE + 2*B_TILE
#define NSTAGE   3
#define DYN_SMEM (STAGE * NSTAGE)   // 74496 -> 2 CTAs/SM

// scratch (static __device__; no cudaMalloc allowed)
__device__ __half g_Xh [(size_t)MAX_TOTAL * MAX_E];
__device__ __half g_O1h[(size_t)MAX_TOTAL * MAX_H];
__device__ __half g_W1f[(size_t)2 * MAX_H * MAX_E]; // [var][n*E+k]
__device__ __half g_W2f[(size_t)2 * MAX_E * MAX_H]; // [var][n*H+k]
__device__ float  g_pre[(size_t)MAX_TOTAL * MAX_E];
__device__ __half g_bndXh[MAX_B * MAX_E];
__device__ __half g_bndOh[MAX_B * MAX_H];

// ---------------------------------------------------------------------------
// helpers
// ---------------------------------------------------------------------------
__device__ __forceinline__ uint32_t smem_u32(const void* p) {
    return (uint32_t)__cvta_generic_to_shared(p);
}
__device__ __forceinline__ void cp16(uint32_t dst, const void* src) {
    asm volatile("cp.async.cg.shared.global [%0], [%1], 16;" :: "r"(dst), "l"(src) : "memory");
}
__device__ __forceinline__ void cp_commit() {
    asm volatile("cp.async.commit_group;" ::: "memory");
}
__device__ __forceinline__ void cp_wait1() {
    asm volatile("cp.async.wait_group 1;" ::: "memory");
}
__device__ __forceinline__ void ldsm_x4(uint32_t* r, uint32_t a) {
    asm volatile("ldmatrix.sync.aligned.m8n8.x4.shared.b16 {%0,%1,%2,%3}, [%4];"
                 : "=r"(r[0]), "=r"(r[1]), "=r"(r[2]), "=r"(r[3]) : "r"(a));
}
__device__ __forceinline__ void mma_fp16(float* c, const uint32_t* a, const uint32_t* b) {
    asm volatile("mma.sync.aligned.m16n8k16.row.col.f32.f16.f16.f32 "
                 "{%0,%1,%2,%3}, {%4,%5,%6,%7}, {%8,%9}, {%0,%1,%2,%3};"
                 : "+f"(c[0]), "+f"(c[1]), "+f"(c[2]), "+f"(c[3])
                 : "r"(a[0]), "r"(a[1]), "r"(a[2]), "r"(a[3]), "r"(b[0]), "r"(b[1]));
}
// 64B-row tile: byte offset for (row, chunk[0..3]) conflict-free for 8-row ldsm
__device__ __forceinline__ uint32_t swz64(int row, int chunk) {
    return (uint32_t)(row * 64 + ((chunk ^ ((row >> 1) & 3)) << 4));
}

// ---------------------------------------------------------------------------
// prep kernels
// ---------------------------------------------------------------------------
__global__ void split_x_kernel(const float* __restrict__ x, size_t n)
{
    size_t i = ((size_t)blockIdx.x * blockDim.x + threadIdx.x) * 4;
    size_t stride = (size_t)gridDim.x * blockDim.x * 4;
    for (; i < n; i += stride) {
        float4 v = *(const float4*)(x + i);
        *(__half2*)(g_Xh + i)     = __floats2half2_rn(v.x, v.y);
        *(__half2*)(g_Xh + i + 2) = __floats2half2_rn(v.z, v.w);
    }
}

__global__ void pack_w_kernel(const float* __restrict__ w1,
                              const float* __restrict__ w2, int E, int H)
{
    size_t stride = (size_t)gridDim.x * blockDim.x;
    size_t i0 = (size_t)blockIdx.x * blockDim.x + threadIdx.x;
    size_t n1 = (size_t)H * E;
    for (size_t i = i0; i < n1; i += stride) {
        g_W1f[i]      = __float2half_rn(w1[i * 2]);
        g_W1f[n1 + i] = __float2half_rn(w1[i * 2 + 1]);
    }
    size_t n2 = (size_t)E * H;
    for (size_t i = i0; i < n2; i += stride) {
        g_W2f[i]      = __float2half_rn(w2[i * 2]);
        g_W2f[n2 + i] = __float2half_rn(w2[i * 2 + 1]);
    }
}

__global__ void prep_bnd_kernel(const float* __restrict__ lf1,
                                const float* __restrict__ lf2,
                                const float* __restrict__ w1,
                                const float* __restrict__ b1,
                                const int*   __restrict__ lens,
                                const int*   __restrict__ maxlen_ptr,
                                int E, int H)
{
    int b = blockIdx.x;
    int L = lens[b];
    int ml = maxlen_ptr ? maxlen_ptr[0] : 4096;
    bool full = (L == ml);
    for (int i = threadIdx.x; i < E; i += blockDim.x) {
        float v = full ? lf1[(size_t)b * E + i] : 0.f;
        g_bndXh[(size_t)b * E + i] = __float2half_rn(v);
    }
    int s0 = ml - L;
    for (int n = threadIdx.x; n < H; n += blockDim.x) {
        float v;
        if (full) {
            v = lf2[(size_t)b * H + n];
        } else {
            v = b1[n];
            if (s0 == 1) {
                const float* wr = w1 + (size_t)n * E * 2;
                float acc = 0.f;
                for (int k = 0; k < E; k++) acc += wr[(size_t)k * 2] * lf1[(size_t)b * E + k];
                v += acc;
            }
        }
        g_bndOh[(size_t)b * H + n] = __float2half_rn(v);
    }
}

// ---------------------------------------------------------------------------
// GEMM: C[t,n] = W0 @ A[t-1] + W1 @ A[t]  (+bias). A tile has BM+1 rows
// (row j = token m0-1+j, clamped to [0, M-1]); prev reads j, cur j+1.
// ---------------------------------------------------------------------------
template<bool STAGE2>
__global__ __launch_bounds__(256, 2)
void conv_tc(const __half* __restrict__ srcH,
             const __half* __restrict__ Wf,
             const float* __restrict__ bias,
             int M, int Nfull, int K, uint32_t wvar,
             float* __restrict__ outF,
             __half* __restrict__ outH)
{
    extern __shared__ char sm[];
    const uint32_t sbase = smem_u32(sm);
    const int tid = threadIdx.x;
    const int lane = tid & 31;
    const int wid = tid >> 5;
    const int m0 = blockIdx.y * 128;
    const int n0 = blockIdx.x * 128;

    // ---- A loader: 129 rows x 4 chunks = 516 cp16 over 256 threads (<=3 ea)
    uint32_t aoff[3]; uint32_t adst[3]; bool aval[3];
    #pragma unroll
    for (int i = 0; i < 3; i++) {
        int s = tid + i * 256;
        aval[i] = (s < 516);
        int row = aval[i] ? (s >> 2) : 0;
        int c   = s & 3;
        int tok = m0 - 1 + row;
        if (tok < 0) tok = 0;
        if (tok >= M) tok = M - 1;
        aoff[i] = (uint32_t)tok * (uint32_t)K + (uint32_t)(c * 8);
        adst[i] = swz64(row, c);
    }
    // ---- B loader: 2 variants x 128 rows x 4 chunks = 1024 cp16 (4 each)
    uint32_t boff[4]; uint32_t bdst[4];
    #pragma unroll
    for (int i = 0; i < 4; i++) {
        int s = tid + i * 256;
        int var = s >> 9;
        int row = (s >> 2) & 127;
        int c   = s & 3;
        boff[i] = (uint32_t)var * wvar + (uint32_t)(n0 + row) * (uint32_t)K
                + (uint32_t)(c * 8);
        bdst[i] = (uint32_t)(B_OFF + var * B_TILE) + swz64(row, c);
    }

    // ---- mma lane constants: 8 warps, 2 m-bands x 4 n-bands of 64x32 -------
    const int wm = wid & 1;
    const int wn = wid >> 1;
    const int mbase = wm * 64;
    const int nbase = wn * 32;
    const int a_row_off = ((lane >> 3) & 1) * 8 + (lane & 7);
    const int a_kh = lane >> 4;
    const int b_row_off = ((lane >> 4) & 1) * 8 + (lane & 7);
    const int b_h = (lane >> 3) & 1;

    float acc[4][4][4];
    #pragma unroll
    for (int mi = 0; mi < 4; mi++)
        #pragma unroll
        for (int ni = 0; ni < 4; ni++)
            #pragma unroll
            for (int e = 0; e < 4; e++) acc[mi][ni][e] = 0.f;

    auto issue = [&](int it) {
        uint32_t sb = sbase + (it % NSTAGE) * STAGE;
        uint32_t koff = (uint32_t)it * 32u;
        #pragma unroll
        for (int i = 0; i < 3; i++)
            if (aval[i]) cp16(sb + adst[i], srcH + aoff[i] + koff);
        #pragma unroll
        for (int i = 0; i < 4; i++)
            cp16(sb + bdst[i], Wf + boff[i] + koff);
        cp_commit();
    };

    const int niter = K >> 5;
    issue(0); issue(1);

    for (int it = 0; it < niter; ++it) {
        cp_wait1();               // group it complete
        __syncthreads();          // slot (it+2)%3 free (computed at it-1)
        if (it + 2 < niter) issue(it + 2);
        else cp_commit();         // empty group keeps count uniform

        const uint32_t base = sbase + (it % NSTAGE) * STAGE;
        #pragma unroll
        for (int ks = 0; ks < 2; ks++) {
            // B fragments: 2 variants x 2 ldsm_x4 covering 32 n
            uint32_t bb[2][8];
            #pragma unroll
            for (int v = 0; v < 2; v++)
                #pragma unroll
                for (int g = 0; g < 2; g++) {
                    int row = nbase + g * 16 + b_row_off;
                    ldsm_x4(&bb[v][g * 4],
                            base + B_OFF + v * B_TILE + swz64(row, ks * 2 + b_h));
                }
            // products: prev (A rows j) -> W0, cur (A rows j+1) -> W1
            #pragma unroll
            for (int av = 0; av < 2; av++) {
                uint32_t a[4][4];
                #pragma unroll
                for (int mi = 0; mi < 4; mi++) {
                    int j = mbase + mi * 16 + a_row_off + av;
                    ldsm_x4(a[mi], base + swz64(j, ks * 2 + a_kh));
                }
                #pragma unroll
                for (int ni = 0; ni < 4; ni++)
                    #pragma unroll
                    for (int mi = 0; mi < 4; mi++)
                        mma_fp16(acc[mi][ni], a[mi], &bb[av][ni * 2]);
            }
        }
    }

    // ---- epilogue (no resid: both stages identical footprint) --------------
    const int erow = lane >> 2;
    const int ecol = (lane & 3) * 2;
    #pragma unroll
    for (int mi = 0; mi < 4; mi++) {
        int r0 = m0 + mbase + mi * 16 + erow;
        int r1 = r0 + 8;
        #pragma unroll
        for (int ni = 0; ni < 4; ni++) {
            int c = n0 + nbase + ni * 8 + ecol;
            float bx = bias[c], by = bias[c + 1];
            float v00 = acc[mi][ni][0] + bx, v01 = acc[mi][ni][1] + by;
            float v10 = acc[mi][ni][2] + bx, v11 = acc[mi][ni][3] + by;
            if (STAGE2) {
                if (r0 < M)
                    *(float2*)(outF + (size_t)r0 * Nfull + c) = make_float2(v00, v01);
                if (r1 < M)
                    *(float2*)(outF + (size_t)r1 * Nfull + c) = make_float2(v10, v11);
            } else {
                if (r0 < M)
                    *(__half2*)(outH + (size_t)r0 * Nfull + c) = __floats2half2_rn(v00, v01);
                if (r1 < M)
                    *(__half2*)(outH + (size_t)r1 * Nfull + c) = __floats2half2_rn(v10, v11);
            }
        }
    }
}

// ---------------------------------------------------------------------------
// fixups: correct prev-product at the B sequence-start tokens (exact).
// One warp per output element; lanes stride k (coalesced weight reads).
// ---------------------------------------------------------------------------
__global__ void fixup1_kernel(const int* __restrict__ start, int E, int H, int BH)
{
    int gid = blockIdx.x * 8 + (threadIdx.x >> 5);
    if (gid >= BH) return;
    int lane = threadIdx.x & 31;
    int b = gid / H;
    int n = gid - b * H;
    int t = start[b];
    int tp = (t > 0) ? (t - 1) : 0;
    const __half2* xu = (const __half2*)(g_Xh + (size_t)tp * E);
    const __half2* xb = (const __half2*)(g_bndXh + (size_t)b * E);
    const __half2* w  = (const __half2*)(g_W1f + (size_t)n * E);  // W1_0
    float acc = 0.f;
    int half_n = E >> 1;
    for (int i = lane; i < half_n; i += 32) {
        float2 d  = __half22float2(__hsub2(xb[i], xu[i]));
        float2 wf = __half22float2(w[i]);
        acc += d.x * wf.x + d.y * wf.y;
    }
    #pragma unroll
    for (int o = 16; o; o >>= 1) acc += __shfl_xor_sync(~0u, acc, o);
    if (lane == 0) {
        size_t off = (size_t)t * H + n;
        g_O1h[off] = __float2half_rn(__half2float(g_O1h[off]) + acc);
    }
}

__global__ void fixup2_kernel(const int* __restrict__ start, int E, int H, int BE)
{
    int gid = blockIdx.x * 8 + (threadIdx.x >> 5);
    if (gid >= BE) return;
    int lane = threadIdx.x & 31;
    int b = gid / E;
    int n = gid - b * E;
    int t = start[b];
    int tp = (t > 0) ? (t - 1) : 0;
    const __half2* ou = (const __half2*)(g_O1h + (size_t)tp * H);  // post-fixup1
    const __half2* ob = (const __half2*)(g_bndOh + (size_t)b * H);
    const __half2* w  = (const __half2*)(g_W2f + (size_t)n * H);   // W2_0
    float acc = 0.f;
    int half_n = H >> 1;
    for (int i = lane; i < half_n; i += 32) {
        float2 d  = __half22float2(__hsub2(ob[i], ou[i]));
        float2 wf = __half22float2(w[i]);
        acc += d.x * wf.x + d.y * wf.y;
    }
    #pragma unroll
    for (int o = 16; o; o >>= 1) acc += __shfl_xor_sync(~0u, acc, o);
    if (lane == 0)
        g_pre[(size_t)t * E + n] += acc;
}

// ---------------------------------------------------------------------------
// rmsnorm with fused residual: out = gamma * (pre + x) * rsqrt(mean((pre+x)^2))
// ---------------------------------------------------------------------------
__global__ __launch_bounds__(256)
void rmsnorm_kernel(const float* __restrict__ pre,
                    const float* __restrict__ x,
                    const float* __restrict__ gamma,
                    float* __restrict__ out, int E, float invE)
{
    __shared__ float srow[MAX_E];
    __shared__ float red[32];
    int t = blockIdx.x;
    const float* prow = pre + (size_t)t * E;
    const float* xrow = x + (size_t)t * E;
    float ss = 0.f;
    for (int i = threadIdx.x * 4; i < E; i += blockDim.x * 4) {
        float4 p = *(const float4*)(prow + i);
        float4 r = *(const float4*)(xrow + i);
        p.x += r.x; p.y += r.y; p.z += r.z; p.w += r.w;
        *(float4*)(srow + i) = p;
        ss += p.x * p.x + p.y * p.y + p.z * p.z + p.w * p.w;
    }
    #pragma unroll
    for (int o = 16; o; o >>= 1) ss += __shfl_xor_sync(~0u, ss, o);
    if ((threadIdx.x & 31) == 0) red[threadIdx.x >> 5] = ss;
    __syncthreads();
    if (threadIdx.x < 32) {
        float v = (threadIdx.x < (blockDim.x >> 5)) ? red[threadIdx.x] : 0.f;
        #pragma unroll
        for (int o = 16; o; o >>= 1) v += __shfl_xor_sync(~0u, v, o);
        if (threadIdx.x == 0) red[0] = v;
    }
    __syncthreads();
    float scale = rsqrtf(red[0] * invE + 1e-6f);
    for (int i = threadIdx.x * 4; i < E; i += blockDim.x * 4) {
        float4 p = *(const float4*)(srow + i);
        float4 g = *(const float4*)(gamma + i);
        p.x *= scale * g.x; p.y *= scale * g.y;
        p.z *= scale * g.z; p.w *= scale * g.w;
        *(float4*)(out + (size_t)t * E + i) = p;
    }
}

__global__ void lf_kernel(const float* __restrict__ inputs,
                          const int* __restrict__ start,
                          const int* __restrict__ lens,
                          int B, int E, int H, int total,
                          float* __restrict__ out, long long out_size)
{
    int b = blockIdx.x;
    int last = start[b] + lens[b] - 1;
    long long base1 = (long long)total * E;
    long long base2 = base1 + (long long)B * E;
    for (int i = threadIdx.x; i < E; i += blockDim.x) {
        long long o = base1 + (long long)b * E + i;
        if (o < out_size) out[o] = inputs[(size_t)last * E + i];
    }
    for (int n = threadIdx.x; n < H; n += blockDim.x) {
        long long o = base2 + (long long)b * H + n;
        if (o < out_size) out[o] = __half2float(g_O1h[(size_t)last * H + n]);
    }
}

__global__ void fallback_kernel(float* out, int n) {
    int i = blockIdx.x * blockDim.x + threadIdx.x;
    if (i < n) out[i] = 0.f;
}

// ---------------------------------------------------------------------------
extern "C" void kernel_launch(void* const* d_in, const int* in_sizes, int n_in,
                              void* d_out, int out_size)
{
    const float* inputs = (const float*)d_in[0];
    const float* lf1    = (const float*)d_in[1];
    const float* lf2    = (const float*)d_in[2];
    const float* w1     = (const float*)d_in[3];
    const float* b1     = (const float*)d_in[4];
    const float* w2     = (const float*)d_in[5];
    const float* b2     = (const float*)d_in[6];
    const float* gamma  = (const float*)d_in[7];
    const int*   start  = (const int*)d_in[8];
    const int*   lens   = (const int*)d_in[9];
    const int*   maxlen = (n_in > 10) ? (const int*)d_in[10] : nullptr;

    const int E = in_sizes[7];
    const int H = in_sizes[4];
    const int total = in_sizes[0] / E;
    const int B = in_sizes[9];
    float* out = (float*)d_out;

    if (E > MAX_E || H > MAX_H || total > MAX_TOTAL || B > MAX_B ||
        (E & 127) || (H & 127) || (E & 31) || (H & 31)) {
        fallback_kernel<<<(out_size + 255) / 256, 256>>>(out, out_size);
        return;
    }

    __half *pXh, *pO1h, *pW1f, *pW2f;
    float *pPre;
    cudaGetSymbolAddress((void**)&pXh,  g_Xh);
    cudaGetSymbolAddress((void**)&pO1h, g_O1h);
    cudaGetSymbolAddress((void**)&pW1f, g_W1f);
    cudaGetSymbolAddress((void**)&pW2f, g_W2f);
    cudaGetSymbolAddress((void**)&pPre, g_pre);

    cudaFuncSetAttribute(conv_tc<false>, cudaFuncAttributeMaxDynamicSharedMemorySize, DYN_SMEM);
    cudaFuncSetAttribute(conv_tc<true>,  cudaFuncAttributeMaxDynamicSharedMemorySize, DYN_SMEM);

    split_x_kernel<<<512, 256>>>(inputs, (size_t)total * E);
    pack_w_kernel<<<512, 256>>>(w1, w2, E, H);
    prep_bnd_kernel<<<B, 256>>>(lf1, lf2, w1, b1, lens, maxlen, E, H);

    // Stage 1: O1 = X[t-1]@W1_0 + X[t]@W1_1 + b1   (M=total, N=H, K=E)
    {
        dim3 grid(H / 128, (total + 127) / 128);
        conv_tc<false><<<grid, 256, DYN_SMEM>>>(pXh, pW1f, b1,
                                                total, H, E, (uint32_t)(H * E),
                                                nullptr, pO1h);
    }
    fixup1_kernel<<<(B * H + 7) / 8, 256>>>(start, E, H, B * H);
    // Stage 2: pre = O1[t-1]@W2_0 + O1[t]@W2_1 + b2  (M=total, N=E, K=H)
    {
        dim3 grid(E / 128, (total + 127) / 128);
        conv_tc<true><<<grid, 256, DYN_SMEM>>>(pO1h, pW2f, b2,
                                               total, E, H, (uint32_t)(E * H),
                                               pPre, nullptr);
    }
    fixup2_kernel<<<(B * E + 7) / 8, 256>>>(start, E, H, B * E);
    rmsnorm_kernel<<<total, 256>>>(pPre, inputs, gamma, out, E, 1.f / (float)E);
    lf_kernel<<<B, 256>>>(inputs, start, lens, B, E, H, total,
                          out, (long long)out_size);
}